// round 6
// baseline (speedup 1.0000x reference)
#include <cuda_runtime.h>

#define B_TOT 4096
#define HID 128
#define NCELL 81
#define LN_EPS 1e-5f

typedef unsigned long long ull;

__device__ __forceinline__ ull ffma2(ull a, ull b, ull c) {
    ull d; asm("fma.rn.f32x2 %0, %1, %2, %3;" : "=l"(d) : "l"(a), "l"(b), "l"(c)); return d;
}
__device__ __forceinline__ ull pack2(float x, float y) {
    ull d; asm("mov.b64 %0, {%1, %2};" : "=l"(d) : "f"(x), "f"(y)); return d;
}
__device__ __forceinline__ float2 unpk(ull v) {
    float2 r; asm("mov.b64 {%0, %1}, %2;" : "=f"(r.x), "=f"(r.y) : "l"(v)); return r;
}
union F4 { float4 f; ull u[2]; };

// ---------------- static device workspace ----------------
__device__ float g_h[NCELL][B_TOT][HID];
__device__ float g_c[NCELL][B_TOT][HID];
__device__ float g_z [B_TOT][256];
__device__ float g_y1[B_TOT][256];
__device__ float g_y2[B_TOT][128];
__device__ float g_y3[B_TOT];
__device__ float g_mu[256];
__device__ float g_rstd[256];

__device__ __forceinline__ float sigmf(float v) { return 1.f / (1.f + expf(-v)); }

// ---------------- smem layout (floats) ----------------
#define PP 133
#define PA 68     // A_T pitch (k-major, 32 x 64), 16B-aligned rows
#define PW 132    // W_T pitch (k-major, 32 x 128)
#define PG 516    // gates G_T pitch (k-major, 32 x 512)
#define SM_PH  0
#define SM_PC  (64 * PP)
#define SM_SCR (2 * 64 * PP)            // 17024
#define ACH (32 * PA)                   // 2176 per A buf
#define WCH (32 * PW)                   // 4224 per W buf
#define GCH (32 * PG)                   // 16512 per gates buf
#define CELL_SMEM_FLOATS (SM_SCR + 2 * GCH)   // 17024 + 33024 = 50048
#define CELL_SMEM_BYTES (CELL_SMEM_FLOATS * 4)

#define NTHR 512

// ---------------------------------------------------------------------------
// GEMM [64,384]x[384,128]^T + bias + LayerNorm -> out_s (pitch PP)
// 512 threads: ty = tid&15 (rows 4ty..), tx = tid>>4 (0..31, cols 4tx..)
__device__ __forceinline__ void gemm_ln(
    const float* s0, const float* s1, const float* s2,
    const float* __restrict__ Wk, const float* __restrict__ biask,
    const float* __restrict__ lng, const float* __restrict__ lnb,
    float* AT0, float* WT0, float* out_s,
    int tid, int ty, int tx, int b0)
{
    ull acc[4][2];
#pragma unroll
    for (int r = 0; r < 4; r++) { acc[r][0] = 0ull; acc[r][1] = 0ull; }

    const float* srcs[3] = { s0, s1, s2 };

    // prologue: chunk 0 direct load (transposed store)
    {
        const float* s = srcs[0];
        {
            int row = tid >> 3; int c4 = (tid & 7) << 2;
            float4 v = make_float4(0.f, 0.f, 0.f, 0.f);
            if (s) v = *(const float4*)(s + (size_t)(b0 + row) * HID + c4);
            AT0[(c4 + 0) * PA + row] = v.x; AT0[(c4 + 1) * PA + row] = v.y;
            AT0[(c4 + 2) * PA + row] = v.z; AT0[(c4 + 3) * PA + row] = v.w;
        }
#pragma unroll
        for (int it = 0; it < 2; it++) {
            int idx = it * NTHR + tid; int n = idx >> 3; int c4 = (idx & 7) << 2;
            float4 v = *(const float4*)(Wk + n * 384 + c4);
            WT0[(c4 + 0) * PW + n] = v.x; WT0[(c4 + 1) * PW + n] = v.y;
            WT0[(c4 + 2) * PW + n] = v.z; WT0[(c4 + 3) * PW + n] = v.w;
        }
    }
    __syncthreads();

#pragma unroll 1
    for (int kc = 0; kc < 12; kc++) {
        // prefetch next chunk into registers
        float4 rA, rW[2];
        bool pre = (kc < 11);
        if (pre) {
            int kn = kc + 1;
            const float* s = srcs[kn >> 2];
            int colb = (kn & 3) << 5;
            {
                int row = tid >> 3; int c4 = (tid & 7) << 2;
                rA = make_float4(0.f, 0.f, 0.f, 0.f);
                if (s) rA = *(const float4*)(s + (size_t)(b0 + row) * HID + colb + c4);
            }
#pragma unroll
            for (int it = 0; it < 2; it++) {
                int idx = it * NTHR + tid; int n = idx >> 3; int c4 = (idx & 7) << 2;
                rW[it] = *(const float4*)(Wk + n * 384 + (kn << 5) + c4);
            }
        }

        const float* AT = AT0 + (kc & 1) * ACH;
        const float* WT = WT0 + (kc & 1) * WCH;
#pragma unroll 8
        for (int kk = 0; kk < 32; kk++) {
            float4 av = *(const float4*)(AT + kk * PA + 4 * ty);
            ull aa[4];
            aa[0] = pack2(av.x, av.x); aa[1] = pack2(av.y, av.y);
            aa[2] = pack2(av.z, av.z); aa[3] = pack2(av.w, av.w);
            F4 w; w.f = *(const float4*)(WT + kk * PW + 4 * tx);
#pragma unroll
            for (int r = 0; r < 4; r++) {
                acc[r][0] = ffma2(aa[r], w.u[0], acc[r][0]);
                acc[r][1] = ffma2(aa[r], w.u[1], acc[r][1]);
            }
        }

        if (pre) {
            float* ATn = AT0 + ((kc + 1) & 1) * ACH;
            float* WTn = WT0 + ((kc + 1) & 1) * WCH;
            {
                int row = tid >> 3; int c4 = (tid & 7) << 2;
                ATn[(c4 + 0) * PA + row] = rA.x; ATn[(c4 + 1) * PA + row] = rA.y;
                ATn[(c4 + 2) * PA + row] = rA.z; ATn[(c4 + 3) * PA + row] = rA.w;
            }
#pragma unroll
            for (int it = 0; it < 2; it++) {
                int idx = it * NTHR + tid; int n = idx >> 3; int c4 = (idx & 7) << 2;
                WTn[(c4 + 0) * PW + n] = rW[it].x; WTn[(c4 + 1) * PW + n] = rW[it].y;
                WTn[(c4 + 2) * PW + n] = rW[it].z; WTn[(c4 + 3) * PW + n] = rW[it].w;
            }
        }
        __syncthreads();
    }

    // bias + stage for LN
#pragma unroll
    for (int r = 0; r < 4; r++)
#pragma unroll
        for (int q = 0; q < 2; q++) {
            float2 v = unpk(acc[r][q]);
            int col = 4 * tx + 2 * q;
            out_s[(ty * 4 + r) * PP + col]     = v.x + biask[col];
            out_s[(ty * 4 + r) * PP + col + 1] = v.y + biask[col + 1];
        }
    __syncthreads();

    // LayerNorm: 16 warps, warp handles 4 rows, lane covers 4 cols
    int warp = tid >> 5, lane = tid & 31;
#pragma unroll
    for (int rr = 0; rr < 4; rr++) {
        int r = warp * 4 + rr;
        float v0 = out_s[r * PP + lane];
        float v1 = out_s[r * PP + lane + 32];
        float v2 = out_s[r * PP + lane + 64];
        float v3 = out_s[r * PP + lane + 96];
        float s = v0 + v1 + v2 + v3;
        float q = v0 * v0 + v1 * v1 + v2 * v2 + v3 * v3;
#pragma unroll
        for (int o = 16; o; o >>= 1) {
            s += __shfl_xor_sync(0xffffffffu, s, o);
            q += __shfl_xor_sync(0xffffffffu, q, o);
        }
        float mu = s * (1.f / 128.f);
        float var = q * (1.f / 128.f) - mu * mu;
        float rs = rsqrtf(var + LN_EPS);
        out_s[r * PP + lane]      = (v0 - mu) * rs * lng[lane]      + lnb[lane];
        out_s[r * PP + lane + 32] = (v1 - mu) * rs * lng[lane + 32] + lnb[lane + 32];
        out_s[r * PP + lane + 64] = (v2 - mu) * rs * lng[lane + 64] + lnb[lane + 64];
        out_s[r * PP + lane + 96] = (v3 - mu) * rs * lng[lane + 96] + lnb[lane + 96];
    }
    __syncthreads();
}

__device__ __forceinline__ void loadG(const float* __restrict__ Whh, int kc,
                                      float* GT, int tid)
{
#pragma unroll
    for (int it = 0; it < 8; it++) {
        int idx = it * NTHR + tid;
        int m = idx >> 3; int c4 = (idx & 7) << 2;
        float4 v = *(const float4*)(Whh + m * 128 + (kc << 5) + c4);
        GT[(c4 + 0) * PG + m] = v.x; GT[(c4 + 1) * PG + m] = v.y;
        GT[(c4 + 2) * PG + m] = v.z; GT[(c4 + 3) * PG + m] = v.w;
    }
}

__global__ void __launch_bounds__(NTHR) cell_kernel(
    const float* __restrict__ x,
    const float* __restrict__ h_ext, const float* __restrict__ c_ext,
    const float* __restrict__ h_grid0, const float* __restrict__ c_grid0,
    const float* __restrict__ Wh, const float* __restrict__ bh,
    const float* __restrict__ Wc, const float* __restrict__ bc,
    const float* __restrict__ lnh_g, const float* __restrict__ lnh_b,
    const float* __restrict__ lnc_g, const float* __restrict__ lnc_b,
    const float* __restrict__ W_ih, const float* __restrict__ b_ih,
    const float* __restrict__ W_hh, const float* __restrict__ b_hh,
    int diag)
{
    extern __shared__ float sm[];
    float* ph_s = sm + SM_PH;
    float* pc_s = sm + SM_PC;
    float* AT0  = sm + SM_SCR;
    float* WT0  = sm + SM_SCR + 2 * ACH;
    float* GT0  = sm + SM_SCR;

    int tid = threadIdx.x, ty = tid & 15, tx = tid >> 4;
    int b0 = blockIdx.x << 6;

    int i0 = diag > 8 ? diag - 8 : 0;
    int i = i0 + blockIdx.y;
    int j = diag - i;
    int k = i * 9 + j;

    const float *h0, *c0, *h1, *c1;
    if (j > 0)       { h0 = &g_h[k - 1][0][0]; c0 = &g_c[k - 1][0][0]; }
    else if (i == 0) { h0 = h_ext;             c0 = c_ext; }
    else             { h0 = 0;                 c0 = 0; }
    if (i > 0)       { h1 = &g_h[k - 9][0][0]; c1 = &g_c[k - 9][0][0]; }
    else             { h1 = 0;                 c1 = 0; }
    const float* h2 = h_grid0 + (size_t)k * B_TOT * HID;
    const float* c2 = c_grid0 + (size_t)k * B_TOT * HID;

    gemm_ln(h0, h1, h2, Wh + (size_t)k * 128 * 384, bh + k * 128,
            lnh_g + k * 128, lnh_b + k * 128, AT0, WT0, ph_s, tid, ty, tx, b0);
    gemm_ln(c0, c1, c2, Wc + (size_t)k * 128 * 384, bc + k * 128,
            lnc_g + k * 128, lnc_b + k * 128, AT0, WT0, pc_s, tid, ty, tx, b0);

    // ---- gates GEMM: [64,128] (ph_s) x [128,512]^T
    const float* Whh = W_hh + (size_t)k * 512 * 128;
    ull accG[4][4][2];
#pragma unroll
    for (int g = 0; g < 4; g++)
#pragma unroll
        for (int r = 0; r < 4; r++) { accG[g][r][0] = 0ull; accG[g][r][1] = 0ull; }

    loadG(Whh, 0, GT0, tid);
    __syncthreads();

#pragma unroll 1
    for (int kc = 0; kc < 4; kc++) {
        if (kc < 3) loadG(Whh, kc + 1, GT0 + ((kc + 1) & 1) * GCH, tid);
        const float* GT = GT0 + (kc & 1) * GCH;
        int kcb = kc << 5;
#pragma unroll 4
        for (int kk = 0; kk < 32; kk++) {
            ull aa[4];
#pragma unroll
            for (int r = 0; r < 4; r++) {
                float a = ph_s[(4 * ty + r) * PP + kcb + kk];
                aa[r] = pack2(a, a);
            }
#pragma unroll
            for (int g = 0; g < 4; g++) {
                F4 w; w.f = *(const float4*)(GT + kk * PG + g * 128 + 4 * tx);
#pragma unroll
                for (int r = 0; r < 4; r++) {
                    accG[g][r][0] = ffma2(aa[r], w.u[0], accG[g][r][0]);
                    accG[g][r][1] = ffma2(aa[r], w.u[1], accG[g][r][1]);
                }
            }
        }
        __syncthreads();
    }

    // ---- LSTM elementwise
    const float* bih = b_ih + k * 512;
    const float* bhh = b_hh + k * 512;
    const float* wih = W_ih + k * 512;
#pragma unroll
    for (int r = 0; r < 4; r++) {
        int row = ty * 4 + r;
        float xb = x[(size_t)(b0 + row) * 81 + k];
#pragma unroll
        for (int q = 0; q < 2; q++) {
            float2 ig2 = unpk(accG[0][r][q]);
            float2 fg2 = unpk(accG[1][r][q]);
            float2 gg2 = unpk(accG[2][r][q]);
            float2 og2 = unpk(accG[3][r][q]);
#pragma unroll
            for (int e = 0; e < 2; e++) {
                int col = 4 * tx + 2 * q + e;
                float igv = (e ? ig2.y : ig2.x) + bih[col]       + bhh[col]       + xb * wih[col];
                float fgv = (e ? fg2.y : fg2.x) + bih[128 + col] + bhh[128 + col] + xb * wih[128 + col];
                float ggv = (e ? gg2.y : gg2.x) + bih[256 + col] + bhh[256 + col] + xb * wih[256 + col];
                float ogv = (e ? og2.y : og2.x) + bih[384 + col] + bhh[384 + col] + xb * wih[384 + col];
                float pcv = pc_s[row * PP + col];
                float cn = sigmf(fgv) * pcv + sigmf(igv) * tanhf(ggv);
                float hn = sigmf(ogv) * tanhf(cn);
                pc_s[row * PP + col] = cn;
                ph_s[row * PP + col] = hn;
            }
        }
    }
    __syncthreads();

    // ---- coalesced writeout
    float* gh = &g_h[k][b0][0];
    float* gc = &g_c[k][b0][0];
#pragma unroll
    for (int it = 0; it < 4; it++) {
        int idx = it * NTHR + tid;
        int r = idx >> 5; int c4 = (idx & 31) << 2;
        float4 vh = make_float4(ph_s[r * PP + c4],     ph_s[r * PP + c4 + 1],
                                ph_s[r * PP + c4 + 2], ph_s[r * PP + c4 + 3]);
        float4 vc = make_float4(pc_s[r * PP + c4],     pc_s[r * PP + c4 + 1],
                                pc_s[r * PP + c4 + 2], pc_s[r * PP + c4 + 3]);
        *(float4*)(gh + r * HID + c4) = vh;
        *(float4*)(gc + r * HID + c4) = vc;
    }
}

// ---------------------------------------------------------------------------
// Head kernels
__global__ void z_kernel(const float* __restrict__ h_ext, const float* __restrict__ c_ext)
{
    int idx = blockIdx.x * 256 + threadIdx.x;
    int b = idx >> 8, c = idx & 255;
    float v;
    if (c < 128) v = g_h[80][b][c]       + h_ext[b * 128 + c];
    else         v = g_c[80][b][c - 128] + c_ext[b * 128 + c - 128];
    g_z[b][c] = v;
}

__global__ void __launch_bounds__(256, 1) head_gemm(
    const float* __restrict__ A, const float* __restrict__ W,
    const float* __restrict__ bias, float* __restrict__ C, int N, int K)
{
    __shared__ float A_s[64 * 33];
    __shared__ float W_s[128 * 33];
    int tid = threadIdx.x, ty = tid & 15, tx = tid >> 4;
    int b0 = blockIdx.x * 64, n0 = blockIdx.y * 128;
    float acc[4][8];
#pragma unroll
    for (int r = 0; r < 4; r++)
#pragma unroll
        for (int c = 0; c < 8; c++) acc[r][c] = 0.f;

    int nk = K >> 5;
#pragma unroll 1
    for (int kc = 0; kc < nk; kc++) {
#pragma unroll
        for (int it = 0; it < 2; it++) {
            int idx = it * 256 + tid; int r = idx >> 3; int c4 = (idx & 7) << 2;
            float4 v = *(const float4*)(A + (size_t)(b0 + r) * K + (kc << 5) + c4);
            float* p = &A_s[r * 33 + c4];
            p[0] = v.x; p[1] = v.y; p[2] = v.z; p[3] = v.w;
        }
#pragma unroll
        for (int it = 0; it < 4; it++) {
            int idx = it * 256 + tid; int n = idx >> 3; int c4 = (idx & 7) << 2;
            float4 v = *(const float4*)(W + (size_t)(n0 + n) * K + (kc << 5) + c4);
            float* p = &W_s[n * 33 + c4];
            p[0] = v.x; p[1] = v.y; p[2] = v.z; p[3] = v.w;
        }
        __syncthreads();
#pragma unroll 4
        for (int kk = 0; kk < 32; kk++) {
            float a[4], w[8];
#pragma unroll
            for (int r = 0; r < 4; r++) a[r] = A_s[(ty * 4 + r) * 33 + kk];
#pragma unroll
            for (int c = 0; c < 8; c++) w[c] = W_s[(tx * 8 + c) * 33 + kk];
#pragma unroll
            for (int r = 0; r < 4; r++)
#pragma unroll
                for (int c = 0; c < 8; c++) acc[r][c] = fmaf(a[r], w[c], acc[r][c]);
        }
        __syncthreads();
    }
#pragma unroll
    for (int r = 0; r < 4; r++)
#pragma unroll
        for (int c = 0; c < 8; c++)
            C[(size_t)(b0 + ty * 4 + r) * N + n0 + tx * 8 + c] = acc[r][c] + bias[n0 + tx * 8 + c];
}

__global__ void bn_stats_kernel(const float* __restrict__ Y, int N)
{
    __shared__ float ss[256], qq[256];
    int col = blockIdx.x, tid = threadIdx.x;
    float s = 0.f, q = 0.f;
    for (int r = tid; r < B_TOT; r += 256) {
        float v = Y[(size_t)r * N + col];
        s += v; q += v * v;
    }
    ss[tid] = s; qq[tid] = q; __syncthreads();
    for (int o = 128; o; o >>= 1) {
        if (tid < o) { ss[tid] += ss[tid + o]; qq[tid] += qq[tid + o]; }
        __syncthreads();
    }
    if (tid == 0) {
        float mu = ss[0] * (1.f / (float)B_TOT);
        float var = qq[0] * (1.f / (float)B_TOT) - mu * mu;
        g_mu[col] = mu;
        g_rstd[col] = rsqrtf(var + LN_EPS);
    }
}

__global__ void bn_relu_kernel(float* __restrict__ Y, const float* __restrict__ g,
                               const float* __restrict__ b, int N)
{
    int idx = blockIdx.x * 256 + threadIdx.x;
    int c = idx & (N - 1);
    float v = (Y[idx] - g_mu[c]) * g_rstd[c] * g[c] + b[c];
    Y[idx] = fmaxf(v, 0.f);
}

__global__ void fc3_kernel(const float* __restrict__ W, const float* __restrict__ bias)
{
    int row = (blockIdx.x * blockDim.x + threadIdx.x) >> 5;
    int lane = threadIdx.x & 31;
    float s = 0.f;
#pragma unroll
    for (int c = lane; c < 128; c += 32) s += g_y2[row][c] * W[c];
#pragma unroll
    for (int o = 16; o; o >>= 1) s += __shfl_xor_sync(0xffffffffu, s, o);
    if (lane == 0) g_y3[row] = s + bias[0];
}

__global__ void final_kernel(const float* __restrict__ g, const float* __restrict__ b,
                             float* __restrict__ out)
{
    __shared__ float ss[1024], qq[1024];
    int tid = threadIdx.x;
    float s = 0.f, q = 0.f;
    for (int r = tid; r < B_TOT; r += 1024) {
        float v = g_y3[r]; s += v; q += v * v;
    }
    ss[tid] = s; qq[tid] = q; __syncthreads();
    for (int o = 512; o; o >>= 1) {
        if (tid < o) { ss[tid] += ss[tid + o]; qq[tid] += qq[tid + o]; }
        __syncthreads();
    }
    float mu = ss[0] * (1.f / (float)B_TOT);
    float var = qq[0] * (1.f / (float)B_TOT) - mu * mu;
    float rs = rsqrtf(var + LN_EPS);
    float gg = g[0], bb = b[0];
    for (int r = tid; r < B_TOT; r += 1024) {
        float v = (g_y3[r] - mu) * rs * gg + bb;
        out[r] = 1.f / (1.f + expf(-v));
    }
}

// ---------------------------------------------------------------------------
extern "C" void kernel_launch(void* const* d_in, const int* in_sizes, int n_in,
                              void* d_out, int out_size)
{
    const float* x     = (const float*)d_in[0];
    const float* h_ext = (const float*)d_in[1];
    const float* c_ext = (const float*)d_in[2];
    const float* h_g0  = (const float*)d_in[3];
    const float* c_g0  = (const float*)d_in[4];
    const float* Wh    = (const float*)d_in[5];
    const float* bh    = (const float*)d_in[6];
    const float* Wc    = (const float*)d_in[7];
    const float* bc    = (const float*)d_in[8];
    const float* lnh_g = (const float*)d_in[9];
    const float* lnh_b = (const float*)d_in[10];
    const float* lnc_g = (const float*)d_in[11];
    const float* lnc_b = (const float*)d_in[12];
    const float* W_ih  = (const float*)d_in[13];
    const float* b_ih  = (const float*)d_in[14];
    const float* W_hh  = (const float*)d_in[15];
    const float* b_hh  = (const float*)d_in[16];
    const float* fc1W  = (const float*)d_in[17];
    const float* fc1b  = (const float*)d_in[18];
    const float* bn1g  = (const float*)d_in[19];
    const float* bn1b  = (const float*)d_in[20];
    const float* fc2W  = (const float*)d_in[21];
    const float* fc2b  = (const float*)d_in[22];
    const float* bn2g  = (const float*)d_in[23];
    const float* bn2b  = (const float*)d_in[24];
    const float* fc3W  = (const float*)d_in[25];
    const float* fc3b  = (const float*)d_in[26];
    const float* bnog  = (const float*)d_in[27];
    const float* bnob  = (const float*)d_in[28];
    float* out = (float*)d_out;

    cudaFuncSetAttribute(cell_kernel, cudaFuncAttributeMaxDynamicSharedMemorySize,
                         CELL_SMEM_BYTES);

    for (int d = 0; d <= 16; d++) {
        int ilo = d > 8 ? d - 8 : 0;
        int ihi = d < 8 ? d : 8;
        int nc = ihi - ilo + 1;
        cell_kernel<<<dim3(64, nc), NTHR, CELL_SMEM_BYTES>>>(
            x, h_ext, c_ext, h_g0, c_g0, Wh, bh, Wc, bc,
            lnh_g, lnh_b, lnc_g, lnc_b, W_ih, b_ih, W_hh, b_hh, d);
    }

    float *zp, *y1p, *y2p;
    cudaGetSymbolAddress((void**)&zp,  g_z);
    cudaGetSymbolAddress((void**)&y1p, g_y1);
    cudaGetSymbolAddress((void**)&y2p, g_y2);

    z_kernel<<<4096, 256>>>(h_ext, c_ext);
    head_gemm<<<dim3(64, 2), 256>>>(zp, fc1W, fc1b, y1p, 256, 256);
    bn_stats_kernel<<<256, 256>>>(y1p, 256);
    bn_relu_kernel<<<4096, 256>>>(y1p, bn1g, bn1b, 256);
    head_gemm<<<dim3(64, 1), 256>>>(y1p, fc2W, fc2b, y2p, 128, 256);
    bn_stats_kernel<<<128, 256>>>(y2p, 128);
    bn_relu_kernel<<<2048, 256>>>(y2p, bn2g, bn2b, 128);
    fc3_kernel<<<512, 256>>>(fc3W, fc3b);
    final_kernel<<<1, 1024>>>(bnog, bnob, out);
}

// round 7
// speedup vs baseline: 1.0021x; 1.0021x over previous
#include <cuda_runtime.h>

#define B_TOT 4096
#define HID 128
#define NCELL 81
#define LN_EPS 1e-5f

typedef unsigned long long ull;

__device__ __forceinline__ ull ffma2(ull a, ull b, ull c) {
    ull d; asm("fma.rn.f32x2 %0, %1, %2, %3;" : "=l"(d) : "l"(a), "l"(b), "l"(c)); return d;
}
__device__ __forceinline__ ull pack2(float x, float y) {
    ull d; asm("mov.b64 %0, {%1, %2};" : "=l"(d) : "f"(x), "f"(y)); return d;
}
__device__ __forceinline__ float2 unpk(ull v) {
    float2 r; asm("mov.b64 {%0, %1}, %2;" : "=f"(r.x), "=f"(r.y) : "l"(v)); return r;
}
union F4 { float4 f; ull u[2]; };

// ---------------- static device workspace ----------------
__device__ float g_h[NCELL][B_TOT][HID];
__device__ float g_c[NCELL][B_TOT][HID];
__device__ float g_z [B_TOT][256];
__device__ float g_y1[B_TOT][256];
__device__ float g_y2[B_TOT][128];
__device__ float g_y3[B_TOT];
__device__ float g_mu[256];
__device__ float g_rstd[256];

__device__ __forceinline__ float sigmf(float v) { return 1.f / (1.f + expf(-v)); }

// ---------------- smem layout (floats) ----------------
#define PP 133
#define PA 68     // A_T pitch (k-major, 32 x 64), 16B-aligned rows
#define PW 132    // W_T pitch (k-major, 32 x 128)
#define PG 516    // gates G_T pitch (k-major, 32 x 512)
#define SM_PH  0
#define SM_PC  (64 * PP)
#define SM_SCR (2 * 64 * PP)            // 17024
#define ACH (32 * PA)                   // 2176 per A buf
#define WCH (32 * PW)                   // 4224 per W buf
#define GCH (32 * PG)                   // 16512 per gates buf
#define CELL_SMEM_FLOATS (SM_SCR + 2 * GCH)   // 17024 + 33024 = 50048
#define CELL_SMEM_BYTES (CELL_SMEM_FLOATS * 4)

#define NTHR 512

// ---------------------------------------------------------------------------
// GEMM [64,384]x[384,128]^T + bias + LayerNorm -> out_s (pitch PP)
// 512 threads: ty = tid&15 (rows 4ty..), tx = tid>>4 (0..31, cols 4tx..)
__device__ __forceinline__ void gemm_ln(
    const float* s0, const float* s1, const float* s2,
    const float* __restrict__ Wk, const float* __restrict__ biask,
    const float* __restrict__ lng, const float* __restrict__ lnb,
    float* AT0, float* WT0, float* out_s,
    int tid, int ty, int tx, int b0)
{
    ull acc[4][2];
#pragma unroll
    for (int r = 0; r < 4; r++) { acc[r][0] = 0ull; acc[r][1] = 0ull; }

    const float* srcs[3] = { s0, s1, s2 };

    // prologue: chunk 0 direct load (transposed store)
    {
        const float* s = srcs[0];
        {
            int row = tid >> 3; int c4 = (tid & 7) << 2;
            float4 v = make_float4(0.f, 0.f, 0.f, 0.f);
            if (s) v = *(const float4*)(s + (size_t)(b0 + row) * HID + c4);
            AT0[(c4 + 0) * PA + row] = v.x; AT0[(c4 + 1) * PA + row] = v.y;
            AT0[(c4 + 2) * PA + row] = v.z; AT0[(c4 + 3) * PA + row] = v.w;
        }
#pragma unroll
        for (int it = 0; it < 2; it++) {
            int idx = it * NTHR + tid; int n = idx >> 3; int c4 = (idx & 7) << 2;
            float4 v = *(const float4*)(Wk + n * 384 + c4);
            WT0[(c4 + 0) * PW + n] = v.x; WT0[(c4 + 1) * PW + n] = v.y;
            WT0[(c4 + 2) * PW + n] = v.z; WT0[(c4 + 3) * PW + n] = v.w;
        }
    }
    __syncthreads();

#pragma unroll 1
    for (int kc = 0; kc < 12; kc++) {
        // prefetch next chunk into registers
        float4 rA, rW[2];
        bool pre = (kc < 11);
        if (pre) {
            int kn = kc + 1;
            const float* s = srcs[kn >> 2];
            int colb = (kn & 3) << 5;
            {
                int row = tid >> 3; int c4 = (tid & 7) << 2;
                rA = make_float4(0.f, 0.f, 0.f, 0.f);
                if (s) rA = *(const float4*)(s + (size_t)(b0 + row) * HID + colb + c4);
            }
#pragma unroll
            for (int it = 0; it < 2; it++) {
                int idx = it * NTHR + tid; int n = idx >> 3; int c4 = (idx & 7) << 2;
                rW[it] = *(const float4*)(Wk + n * 384 + (kn << 5) + c4);
            }
        }

        const float* AT = AT0 + (kc & 1) * ACH;
        const float* WT = WT0 + (kc & 1) * WCH;
#pragma unroll 8
        for (int kk = 0; kk < 32; kk++) {
            float4 av = *(const float4*)(AT + kk * PA + 4 * ty);
            ull aa[4];
            aa[0] = pack2(av.x, av.x); aa[1] = pack2(av.y, av.y);
            aa[2] = pack2(av.z, av.z); aa[3] = pack2(av.w, av.w);
            F4 w; w.f = *(const float4*)(WT + kk * PW + 4 * tx);
#pragma unroll
            for (int r = 0; r < 4; r++) {
                acc[r][0] = ffma2(aa[r], w.u[0], acc[r][0]);
                acc[r][1] = ffma2(aa[r], w.u[1], acc[r][1]);
            }
        }

        if (pre) {
            float* ATn = AT0 + ((kc + 1) & 1) * ACH;
            float* WTn = WT0 + ((kc + 1) & 1) * WCH;
            {
                int row = tid >> 3; int c4 = (tid & 7) << 2;
                ATn[(c4 + 0) * PA + row] = rA.x; ATn[(c4 + 1) * PA + row] = rA.y;
                ATn[(c4 + 2) * PA + row] = rA.z; ATn[(c4 + 3) * PA + row] = rA.w;
            }
#pragma unroll
            for (int it = 0; it < 2; it++) {
                int idx = it * NTHR + tid; int n = idx >> 3; int c4 = (idx & 7) << 2;
                WTn[(c4 + 0) * PW + n] = rW[it].x; WTn[(c4 + 1) * PW + n] = rW[it].y;
                WTn[(c4 + 2) * PW + n] = rW[it].z; WTn[(c4 + 3) * PW + n] = rW[it].w;
            }
        }
        __syncthreads();
    }

    // bias + stage for LN
#pragma unroll
    for (int r = 0; r < 4; r++)
#pragma unroll
        for (int q = 0; q < 2; q++) {
            float2 v = unpk(acc[r][q]);
            int col = 4 * tx + 2 * q;
            out_s[(ty * 4 + r) * PP + col]     = v.x + biask[col];
            out_s[(ty * 4 + r) * PP + col + 1] = v.y + biask[col + 1];
        }
    __syncthreads();

    // LayerNorm: 16 warps, warp handles 4 rows, lane covers 4 cols
    int warp = tid >> 5, lane = tid & 31;
#pragma unroll
    for (int rr = 0; rr < 4; rr++) {
        int r = warp * 4 + rr;
        float v0 = out_s[r * PP + lane];
        float v1 = out_s[r * PP + lane + 32];
        float v2 = out_s[r * PP + lane + 64];
        float v3 = out_s[r * PP + lane + 96];
        float s = v0 + v1 + v2 + v3;
        float q = v0 * v0 + v1 * v1 + v2 * v2 + v3 * v3;
#pragma unroll
        for (int o = 16; o; o >>= 1) {
            s += __shfl_xor_sync(0xffffffffu, s, o);
            q += __shfl_xor_sync(0xffffffffu, q, o);
        }
        float mu = s * (1.f / 128.f);
        float var = q * (1.f / 128.f) - mu * mu;
        float rs = rsqrtf(var + LN_EPS);
        out_s[r * PP + lane]      = (v0 - mu) * rs * lng[lane]      + lnb[lane];
        out_s[r * PP + lane + 32] = (v1 - mu) * rs * lng[lane + 32] + lnb[lane + 32];
        out_s[r * PP + lane + 64] = (v2 - mu) * rs * lng[lane + 64] + lnb[lane + 64];
        out_s[r * PP + lane + 96] = (v3 - mu) * rs * lng[lane + 96] + lnb[lane + 96];
    }
    __syncthreads();
}

__device__ __forceinline__ void loadG(const float* __restrict__ Whh, int kc,
                                      float* GT, int tid)
{
#pragma unroll
    for (int it = 0; it < 8; it++) {
        int idx = it * NTHR + tid;
        int m = idx >> 3; int c4 = (idx & 7) << 2;
        float4 v = *(const float4*)(Whh + m * 128 + (kc << 5) + c4);
        GT[(c4 + 0) * PG + m] = v.x; GT[(c4 + 1) * PG + m] = v.y;
        GT[(c4 + 2) * PG + m] = v.z; GT[(c4 + 3) * PG + m] = v.w;
    }
}

__global__ void __launch_bounds__(NTHR) cell_kernel(
    const float* __restrict__ x,
    const float* __restrict__ h_ext, const float* __restrict__ c_ext,
    const float* __restrict__ h_grid0, const float* __restrict__ c_grid0,
    const float* __restrict__ Wh, const float* __restrict__ bh,
    const float* __restrict__ Wc, const float* __restrict__ bc,
    const float* __restrict__ lnh_g, const float* __restrict__ lnh_b,
    const float* __restrict__ lnc_g, const float* __restrict__ lnc_b,
    const float* __restrict__ W_ih, const float* __restrict__ b_ih,
    const float* __restrict__ W_hh, const float* __restrict__ b_hh,
    int diag)
{
    extern __shared__ float sm[];
    float* ph_s = sm + SM_PH;
    float* pc_s = sm + SM_PC;
    float* AT0  = sm + SM_SCR;
    float* WT0  = sm + SM_SCR + 2 * ACH;
    float* GT0  = sm + SM_SCR;

    int tid = threadIdx.x, ty = tid & 15, tx = tid >> 4;
    int b0 = blockIdx.x << 6;

    int i0 = diag > 8 ? diag - 8 : 0;
    int i = i0 + blockIdx.y;
    int j = diag - i;
    int k = i * 9 + j;

    const float *h0, *c0, *h1, *c1;
    if (j > 0)       { h0 = &g_h[k - 1][0][0]; c0 = &g_c[k - 1][0][0]; }
    else if (i == 0) { h0 = h_ext;             c0 = c_ext; }
    else             { h0 = 0;                 c0 = 0; }
    if (i > 0)       { h1 = &g_h[k - 9][0][0]; c1 = &g_c[k - 9][0][0]; }
    else             { h1 = 0;                 c1 = 0; }
    const float* h2 = h_grid0 + (size_t)k * B_TOT * HID;
    const float* c2 = c_grid0 + (size_t)k * B_TOT * HID;

    gemm_ln(h0, h1, h2, Wh + (size_t)k * 128 * 384, bh + k * 128,
            lnh_g + k * 128, lnh_b + k * 128, AT0, WT0, ph_s, tid, ty, tx, b0);
    gemm_ln(c0, c1, c2, Wc + (size_t)k * 128 * 384, bc + k * 128,
            lnc_g + k * 128, lnc_b + k * 128, AT0, WT0, pc_s, tid, ty, tx, b0);

    // ---- gates GEMM: [64,128] (ph_s) x [128,512]^T
    const float* Whh = W_hh + (size_t)k * 512 * 128;
    ull accG[4][4][2];
#pragma unroll
    for (int g = 0; g < 4; g++)
#pragma unroll
        for (int r = 0; r < 4; r++) { accG[g][r][0] = 0ull; accG[g][r][1] = 0ull; }

    loadG(Whh, 0, GT0, tid);
    __syncthreads();

#pragma unroll 1
    for (int kc = 0; kc < 4; kc++) {
        if (kc < 3) loadG(Whh, kc + 1, GT0 + ((kc + 1) & 1) * GCH, tid);
        const float* GT = GT0 + (kc & 1) * GCH;
        int kcb = kc << 5;
#pragma unroll 4
        for (int kk = 0; kk < 32; kk++) {
            ull aa[4];
#pragma unroll
            for (int r = 0; r < 4; r++) {
                float a = ph_s[(4 * ty + r) * PP + kcb + kk];
                aa[r] = pack2(a, a);
            }
#pragma unroll
            for (int g = 0; g < 4; g++) {
                F4 w; w.f = *(const float4*)(GT + kk * PG + g * 128 + 4 * tx);
#pragma unroll
                for (int r = 0; r < 4; r++) {
                    accG[g][r][0] = ffma2(aa[r], w.u[0], accG[g][r][0]);
                    accG[g][r][1] = ffma2(aa[r], w.u[1], accG[g][r][1]);
                }
            }
        }
        __syncthreads();
    }

    // ---- LSTM elementwise
    const float* bih = b_ih + k * 512;
    const float* bhh = b_hh + k * 512;
    const float* wih = W_ih + k * 512;
#pragma unroll
    for (int r = 0; r < 4; r++) {
        int row = ty * 4 + r;
        float xb = x[(size_t)(b0 + row) * 81 + k];
#pragma unroll
        for (int q = 0; q < 2; q++) {
            float2 ig2 = unpk(accG[0][r][q]);
            float2 fg2 = unpk(accG[1][r][q]);
            float2 gg2 = unpk(accG[2][r][q]);
            float2 og2 = unpk(accG[3][r][q]);
#pragma unroll
            for (int e = 0; e < 2; e++) {
                int col = 4 * tx + 2 * q + e;
                float igv = (e ? ig2.y : ig2.x) + bih[col]       + bhh[col]       + xb * wih[col];
                float fgv = (e ? fg2.y : fg2.x) + bih[128 + col] + bhh[128 + col] + xb * wih[128 + col];
                float ggv = (e ? gg2.y : gg2.x) + bih[256 + col] + bhh[256 + col] + xb * wih[256 + col];
                float ogv = (e ? og2.y : og2.x) + bih[384 + col] + bhh[384 + col] + xb * wih[384 + col];
                float pcv = pc_s[row * PP + col];
                float cn = sigmf(fgv) * pcv + sigmf(igv) * tanhf(ggv);
                float hn = sigmf(ogv) * tanhf(cn);
                pc_s[row * PP + col] = cn;
                ph_s[row * PP + col] = hn;
            }
        }
    }
    __syncthreads();

    // ---- coalesced writeout
    float* gh = &g_h[k][b0][0];
    float* gc = &g_c[k][b0][0];
#pragma unroll
    for (int it = 0; it < 4; it++) {
        int idx = it * NTHR + tid;
        int r = idx >> 5; int c4 = (idx & 31) << 2;
        float4 vh = make_float4(ph_s[r * PP + c4],     ph_s[r * PP + c4 + 1],
                                ph_s[r * PP + c4 + 2], ph_s[r * PP + c4 + 3]);
        float4 vc = make_float4(pc_s[r * PP + c4],     pc_s[r * PP + c4 + 1],
                                pc_s[r * PP + c4 + 2], pc_s[r * PP + c4 + 3]);
        *(float4*)(gh + r * HID + c4) = vh;
        *(float4*)(gc + r * HID + c4) = vc;
    }
}

// ---------------------------------------------------------------------------
// Head kernels
__global__ void z_kernel(const float* __restrict__ h_ext, const float* __restrict__ c_ext)
{
    int idx = blockIdx.x * 256 + threadIdx.x;
    int b = idx >> 8, c = idx & 255;
    float v;
    if (c < 128) v = g_h[80][b][c]       + h_ext[b * 128 + c];
    else         v = g_c[80][b][c - 128] + c_ext[b * 128 + c - 128];
    g_z[b][c] = v;
}

__global__ void __launch_bounds__(256, 1) head_gemm(
    const float* __restrict__ A, const float* __restrict__ W,
    const float* __restrict__ bias, float* __restrict__ C, int N, int K)
{
    __shared__ float A_s[64 * 33];
    __shared__ float W_s[128 * 33];
    int tid = threadIdx.x, ty = tid & 15, tx = tid >> 4;
    int b0 = blockIdx.x * 64, n0 = blockIdx.y * 128;
    float acc[4][8];
#pragma unroll
    for (int r = 0; r < 4; r++)
#pragma unroll
        for (int c = 0; c < 8; c++) acc[r][c] = 0.f;

    int nk = K >> 5;
#pragma unroll 1
    for (int kc = 0; kc < nk; kc++) {
#pragma unroll
        for (int it = 0; it < 2; it++) {
            int idx = it * 256 + tid; int r = idx >> 3; int c4 = (idx & 7) << 2;
            float4 v = *(const float4*)(A + (size_t)(b0 + r) * K + (kc << 5) + c4);
            float* p = &A_s[r * 33 + c4];
            p[0] = v.x; p[1] = v.y; p[2] = v.z; p[3] = v.w;
        }
#pragma unroll
        for (int it = 0; it < 4; it++) {
            int idx = it * 256 + tid; int n = idx >> 3; int c4 = (idx & 7) << 2;
            float4 v = *(const float4*)(W + (size_t)(n0 + n) * K + (kc << 5) + c4);
            float* p = &W_s[n * 33 + c4];
            p[0] = v.x; p[1] = v.y; p[2] = v.z; p[3] = v.w;
        }
        __syncthreads();
#pragma unroll 4
        for (int kk = 0; kk < 32; kk++) {
            float a[4], w[8];
#pragma unroll
            for (int r = 0; r < 4; r++) a[r] = A_s[(ty * 4 + r) * 33 + kk];
#pragma unroll
            for (int c = 0; c < 8; c++) w[c] = W_s[(tx * 8 + c) * 33 + kk];
#pragma unroll
            for (int r = 0; r < 4; r++)
#pragma unroll
                for (int c = 0; c < 8; c++) acc[r][c] = fmaf(a[r], w[c], acc[r][c]);
        }
        __syncthreads();
    }
#pragma unroll
    for (int r = 0; r < 4; r++)
#pragma unroll
        for (int c = 0; c < 8; c++)
            C[(size_t)(b0 + ty * 4 + r) * N + n0 + tx * 8 + c] = acc[r][c] + bias[n0 + tx * 8 + c];
}

__global__ void bn_stats_kernel(const float* __restrict__ Y, int N)
{
    __shared__ float ss[256], qq[256];
    int col = blockIdx.x, tid = threadIdx.x;
    float s = 0.f, q = 0.f;
    for (int r = tid; r < B_TOT; r += 256) {
        float v = Y[(size_t)r * N + col];
        s += v; q += v * v;
    }
    ss[tid] = s; qq[tid] = q; __syncthreads();
    for (int o = 128; o; o >>= 1) {
        if (tid < o) { ss[tid] += ss[tid + o]; qq[tid] += qq[tid + o]; }
        __syncthreads();
    }
    if (tid == 0) {
        float mu = ss[0] * (1.f / (float)B_TOT);
        float var = qq[0] * (1.f / (float)B_TOT) - mu * mu;
        g_mu[col] = mu;
        g_rstd[col] = rsqrtf(var + LN_EPS);
    }
}

__global__ void bn_relu_kernel(float* __restrict__ Y, const float* __restrict__ g,
                               const float* __restrict__ b, int N)
{
    int idx = blockIdx.x * 256 + threadIdx.x;
    int c = idx & (N - 1);
    float v = (Y[idx] - g_mu[c]) * g_rstd[c] * g[c] + b[c];
    Y[idx] = fmaxf(v, 0.f);
}

__global__ void fc3_kernel(const float* __restrict__ W, const float* __restrict__ bias)
{
    int row = (blockIdx.x * blockDim.x + threadIdx.x) >> 5;
    int lane = threadIdx.x & 31;
    float s = 0.f;
#pragma unroll
    for (int c = lane; c < 128; c += 32) s += g_y2[row][c] * W[c];
#pragma unroll
    for (int o = 16; o; o >>= 1) s += __shfl_xor_sync(0xffffffffu, s, o);
    if (lane == 0) g_y3[row] = s + bias[0];
}

__global__ void final_kernel(const float* __restrict__ g, const float* __restrict__ b,
                             float* __restrict__ out)
{
    __shared__ float ss[1024], qq[1024];
    int tid = threadIdx.x;
    float s = 0.f, q = 0.f;
    for (int r = tid; r < B_TOT; r += 1024) {
        float v = g_y3[r]; s += v; q += v * v;
    }
    ss[tid] = s; qq[tid] = q; __syncthreads();
    for (int o = 512; o; o >>= 1) {
        if (tid < o) { ss[tid] += ss[tid + o]; qq[tid] += qq[tid + o]; }
        __syncthreads();
    }
    float mu = ss[0] * (1.f / (float)B_TOT);
    float var = qq[0] * (1.f / (float)B_TOT) - mu * mu;
    float rs = rsqrtf(var + LN_EPS);
    float gg = g[0], bb = b[0];
    for (int r = tid; r < B_TOT; r += 1024) {
        float v = (g_y3[r] - mu) * rs * gg + bb;
        out[r] = 1.f / (1.f + expf(-v));
    }
}

// ---------------------------------------------------------------------------
extern "C" void kernel_launch(void* const* d_in, const int* in_sizes, int n_in,
                              void* d_out, int out_size)
{
    const float* x     = (const float*)d_in[0];
    const float* h_ext = (const float*)d_in[1];
    const float* c_ext = (const float*)d_in[2];
    const float* h_g0  = (const float*)d_in[3];
    const float* c_g0  = (const float*)d_in[4];
    const float* Wh    = (const float*)d_in[5];
    const float* bh    = (const float*)d_in[6];
    const float* Wc    = (const float*)d_in[7];
    const float* bc    = (const float*)d_in[8];
    const float* lnh_g = (const float*)d_in[9];
    const float* lnh_b = (const float*)d_in[10];
    const float* lnc_g = (const float*)d_in[11];
    const float* lnc_b = (const float*)d_in[12];
    const float* W_ih  = (const float*)d_in[13];
    const float* b_ih  = (const float*)d_in[14];
    const float* W_hh  = (const float*)d_in[15];
    const float* b_hh  = (const float*)d_in[16];
    const float* fc1W  = (const float*)d_in[17];
    const float* fc1b  = (const float*)d_in[18];
    const float* bn1g  = (const float*)d_in[19];
    const float* bn1b  = (const float*)d_in[20];
    const float* fc2W  = (const float*)d_in[21];
    const float* fc2b  = (const float*)d_in[22];
    const float* bn2g  = (const float*)d_in[23];
    const float* bn2b  = (const float*)d_in[24];
    const float* fc3W  = (const float*)d_in[25];
    const float* fc3b  = (const float*)d_in[26];
    const float* bnog  = (const float*)d_in[27];
    const float* bnob  = (const float*)d_in[28];
    float* out = (float*)d_out;

    cudaFuncSetAttribute(cell_kernel, cudaFuncAttributeMaxDynamicSharedMemorySize,
                         CELL_SMEM_BYTES);

    for (int d = 0; d <= 16; d++) {
        int ilo = d > 8 ? d - 8 : 0;
        int ihi = d < 8 ? d : 8;
        int nc = ihi - ilo + 1;
        cell_kernel<<<dim3(64, nc), NTHR, CELL_SMEM_BYTES>>>(
            x, h_ext, c_ext, h_g0, c_g0, Wh, bh, Wc, bc,
            lnh_g, lnh_b, lnc_g, lnc_b, W_ih, b_ih, W_hh, b_hh, d);
    }

    float *zp, *y1p, *y2p;
    cudaGetSymbolAddress((void**)&zp,  g_z);
    cudaGetSymbolAddress((void**)&y1p, g_y1);
    cudaGetSymbolAddress((void**)&y2p, g_y2);

    z_kernel<<<4096, 256>>>(h_ext, c_ext);
    head_gemm<<<dim3(64, 2), 256>>>(zp, fc1W, fc1b, y1p, 256, 256);
    bn_stats_kernel<<<256, 256>>>(y1p, 256);
    bn_relu_kernel<<<4096, 256>>>(y1p, bn1g, bn1b, 256);
    head_gemm<<<dim3(64, 1), 256>>>(y1p, fc2W, fc2b, y2p, 128, 256);
    bn_stats_kernel<<<128, 256>>>(y2p, 128);
    bn_relu_kernel<<<2048, 256>>>(y2p, bn2g, bn2b, 128);
    fc3_kernel<<<512, 256>>>(fc3W, fc3b);
    final_kernel<<<1, 1024>>>(bnog, bnob, out);
}

// round 10
// speedup vs baseline: 1.3728x; 1.3699x over previous
#include <cuda_runtime.h>
#include <cuda_fp16.h>
#include <cstdint>
typedef uint32_t u32;

#define B_TOT 4096
#define NCELL 81
#define LN_EPS 1e-5f
#define NTHR 256

__device__ float g_h[NCELL][B_TOT][128];
__device__ float g_c[NCELL][B_TOT][128];
__device__ float g_z [B_TOT][256];
__device__ float g_y1[B_TOT][256];
__device__ float g_y2[B_TOT][128];
__device__ float g_y3[B_TOT];
__device__ float g_mu[256];
__device__ float g_rstd[256];

__device__ __forceinline__ float sigmf(float v){ return 1.f/(1.f+expf(-v)); }

// ---- smem byte offsets ----
#define P_BS  0
#define P_WIH 2048
#define P_X   4096
#define P_BH  4352
#define P_BC  4864
#define P_LHG 5376
#define P_LHB 5888
#define P_LCG 6400
#define P_LCB 6912
#define P0 8448            // staging fp32, pitch 132 floats (64 rows)
#define P1 42240           // ph fp16 chunks: chunk c: hi P1+c*10240, lo +5120
#define P2 83200           // main A/B double buffers; gates B overlays
#define P3 144640          // gate_if fp32 pitch 260 floats
#define SMEM_TOTAL 211200
#define AB(i) (P2 + (i)*10240)           // A chunk: hi 64*80, lo +5120
#define BB(i) (P2 + 20480 + (i)*20480)   // B chunk: hi 128*80, lo +10240
#define GB    (P2)                        // gates B: hi 256*80, lo +20480

__device__ __forceinline__ void mma8(float* d,const u32* a,u32 b0,u32 b1){
    asm volatile("mma.sync.aligned.m16n8k16.row.col.f32.f16.f16.f32 "
        "{%0,%1,%2,%3},{%4,%5,%6,%7},{%8,%9},{%0,%1,%2,%3};"
        : "+f"(d[0]),"+f"(d[1]),"+f"(d[2]),"+f"(d[3])
        : "r"(a[0]),"r"(a[1]),"r"(a[2]),"r"(a[3]),"r"(b0),"r"(b1));
}
__device__ __forceinline__ void cvt2(float ax,float ay,u32&H,u32&L){
    __half2 h=__floats2half2_rn(ax,ay);
    float2 f=__half22float2(h);
    __half2 l=__floats2half2_rn(ax-f.x,ay-f.y);
    H=*(u32*)&h; L=*(u32*)&l;
}

// main GEMM: [64,384]x[384,128]^T -> staging fp32 (P0) + bias
__device__ __forceinline__ void main_gemm(char* smc,
    const float* s0,const float* s1,const float* s2,
    const float* __restrict__ Wk,int b0,int tid,int lane,int w,int biasOff)
{
    float* smf=(float*)smc;
    const float* srcs[3]={s0,s1,s2};
    float acc[8][4];
#pragma unroll
    for(int s=0;s<8;s++){acc[s][0]=0;acc[s][1]=0;acc[s][2]=0;acc[s][3]=0;}
    float4 rA[2],rW[4];
    auto ldc=[&](int kc){
        const float* s=srcs[kc>>2]; int cb=(kc&3)*32;
#pragma unroll
        for(int u=0;u<2;u++){int sl=u*NTHR+tid;int row=sl>>3;int cq=(sl&7)*4;
            rA[u]= s? *(const float4*)(s+(size_t)(b0+row)*128+cb+cq):make_float4(0,0,0,0);}
#pragma unroll
        for(int u=0;u<4;u++){int sl=u*NTHR+tid;int n=sl>>3;int cq=(sl&7)*4;
            rW[u]=*(const float4*)(Wk+(size_t)n*384+kc*32+cq);}
    };
    auto sts=[&](int buf){
#pragma unroll
        for(int u=0;u<2;u++){int sl=u*NTHR+tid;int row=sl>>3;int cq=(sl&7)*4;
            u32 h0,l0,h1,l1; cvt2(rA[u].x,rA[u].y,h0,l0); cvt2(rA[u].z,rA[u].w,h1,l1);
            char* p=smc+AB(buf)+row*80+cq*2;
            *(uint2*)p=make_uint2(h0,h1); *(uint2*)(p+5120)=make_uint2(l0,l1);}
#pragma unroll
        for(int u=0;u<4;u++){int sl=u*NTHR+tid;int n=sl>>3;int cq=(sl&7)*4;
            u32 h0,l0,h1,l1; cvt2(rW[u].x,rW[u].y,h0,l0); cvt2(rW[u].z,rW[u].w,h1,l1);
            char* p=smc+BB(buf)+n*80+cq*2;
            *(uint2*)p=make_uint2(h0,h1); *(uint2*)(p+10240)=make_uint2(l0,l1);}
    };
    ldc(0); sts(0); __syncthreads();
#pragma unroll 1
    for(int kc=0;kc<12;kc++){
        if(kc<11) ldc(kc+1);
        const char* Ah=smc+AB(kc&1); const char* Bh=smc+BB(kc&1);
        int ar=16*(w>>1)+(lane>>2);
#pragma unroll
        for(int kh=0;kh<2;kh++){
            int ao=ar*80+(kh*16+(lane&3)*2)*2;
            u32 ah[4],al[4];
            ah[0]=*(const u32*)(Ah+ao);      ah[1]=*(const u32*)(Ah+ao+640);
            ah[2]=*(const u32*)(Ah+ao+16);   ah[3]=*(const u32*)(Ah+ao+656);
            al[0]=*(const u32*)(Ah+ao+5120); al[1]=*(const u32*)(Ah+ao+5760);
            al[2]=*(const u32*)(Ah+ao+5136); al[3]=*(const u32*)(Ah+ao+5776);
#pragma unroll
            for(int s=0;s<8;s++){
                int bn=64*(w&1)+8*s+(lane>>2);
                int bo=bn*80+(kh*16+(lane&3)*2)*2;
                u32 bh0=*(const u32*)(Bh+bo),       bh1=*(const u32*)(Bh+bo+16);
                u32 bl0=*(const u32*)(Bh+bo+10240), bl1=*(const u32*)(Bh+bo+10256);
                mma8(acc[s],ah,bh0,bh1);
                mma8(acc[s],ah,bl0,bl1);
                mma8(acc[s],al,bh0,bh1);
            }
        }
        if(kc<11) sts((kc+1)&1);
        __syncthreads();
    }
    float* pcf=(float*)(smc+P0);
    const float* bias=(const float*)(smc+biasOff);
    int r=16*(w>>1)+(lane>>2);
#pragma unroll
    for(int s=0;s<8;s++){
        int c=64*(w&1)+8*s+(lane&3)*2;
        pcf[r*132+c]=acc[s][0]+bias[c];   pcf[r*132+c+1]=acc[s][1]+bias[c+1];
        pcf[(r+8)*132+c]=acc[s][2]+bias[c]; pcf[(r+8)*132+c+1]=acc[s][3]+bias[c+1];
    }
}

__device__ __forceinline__ void ln_pass(char* smc,int lane,int w,int gOff,int bOff,int toHalf){
    float* pcf=(float*)(smc+P0);
    const float* g=(const float*)(smc+gOff); const float* b=(const float*)(smc+bOff);
#pragma unroll 1
    for(int rr=0;rr<8;rr++){
        int r=w*8+rr;
        float v[4];
#pragma unroll
        for(int q=0;q<4;q++) v[q]=pcf[r*132+lane+32*q];
        float s=v[0]+v[1]+v[2]+v[3];
        float qq=v[0]*v[0]+v[1]*v[1]+v[2]*v[2]+v[3]*v[3];
#pragma unroll
        for(int o=16;o;o>>=1){ s+=__shfl_xor_sync(~0u,s,o); qq+=__shfl_xor_sync(~0u,qq,o); }
        float mu=s*(1.f/128.f), var=qq*(1.f/128.f)-mu*mu, rs=rsqrtf(var+LN_EPS);
#pragma unroll
        for(int q=0;q<4;q++){
            float nv=(v[q]-mu)*rs*g[lane+32*q]+b[lane+32*q];
            if(toHalf){
                __half hh=__float2half_rn(nv);
                __half hl=__float2half_rn(nv-__half2float(hh));
                *(__half*)(smc+P1+q*10240+r*80+lane*2)=hh;
                *(__half*)(smc+P1+q*10240+5120+r*80+lane*2)=hl;
            } else pcf[r*132+lane+32*q]=nv;
        }
    }
}

__global__ void __launch_bounds__(NTHR) cell_kernel(
    const float* __restrict__ x,
    const float* __restrict__ h_ext,const float* __restrict__ c_ext,
    const float* __restrict__ h_grid0,const float* __restrict__ c_grid0,
    const float* __restrict__ Wh,const float* __restrict__ bh,
    const float* __restrict__ Wc,const float* __restrict__ bc,
    const float* __restrict__ lnh_g,const float* __restrict__ lnh_b,
    const float* __restrict__ lnc_g,const float* __restrict__ lnc_b,
    const float* __restrict__ W_ih,const float* __restrict__ b_ih,
    const float* __restrict__ W_hh,const float* __restrict__ b_hh,int diag)
{
    extern __shared__ char smc[];
    float* smf=(float*)smc;
    int tid=threadIdx.x, lane=tid&31, w=tid>>5;
    int b0=blockIdx.x<<6;
    int i0=diag>8?diag-8:0;
    int i=i0+blockIdx.y, j=diag-i, k=i*9+j;

    {
        const float* bihp=b_ih+k*512; const float* bhhp=b_hh+k*512; const float* wihp=W_ih+k*512;
        for(int t=tid;t<512;t+=NTHR){ smf[P_BS/4+t]=bihp[t]+bhhp[t]; smf[P_WIH/4+t]=wihp[t]; }
        if(tid<64) smf[P_X/4+tid]=x[(size_t)(b0+tid)*81+k];
        if(tid<128){
            smf[P_BH/4+tid]=bh[k*128+tid];    smf[P_BC/4+tid]=bc[k*128+tid];
            smf[P_LHG/4+tid]=lnh_g[k*128+tid];smf[P_LHB/4+tid]=lnh_b[k*128+tid];
            smf[P_LCG/4+tid]=lnc_g[k*128+tid];smf[P_LCB/4+tid]=lnc_b[k*128+tid];
        }
    }
    const float *h0,*c0,*h1,*c1;
    if(j>0){ h0=&g_h[k-1][0][0]; c0=&g_c[k-1][0][0]; }
    else if(i==0){ h0=h_ext; c0=c_ext; }
    else { h0=0; c0=0; }
    if(i>0){ h1=&g_h[k-9][0][0]; c1=&g_c[k-9][0][0]; } else { h1=0; c1=0; }
    const float* h2=h_grid0+(size_t)k*B_TOT*128;
    const float* c2=c_grid0+(size_t)k*B_TOT*128;
    __syncthreads();

    // h GEMM -> LN -> fp16 chunks (gates A)
    main_gemm(smc,h0,h1,h2,Wh+(size_t)k*49152,b0,tid,lane,w,P_BH);
    __syncthreads();
    ln_pass(smc,lane,w,P_LHG,P_LHB,1);
    __syncthreads();
    // c GEMM -> LN -> fp32 in P0
    main_gemm(smc,c0,c1,c2,Wc+(size_t)k*49152,b0,tid,lane,w,P_BC);
    __syncthreads();
    ln_pass(smc,lane,w,P_LCG,P_LCB,0);
    __syncthreads();

    // gates: half0 = i,g ; half1 = f,o
    const float* Whh=W_hh+(size_t)k*65536;
    float* gif=(float*)(smc+P3);
    float* pcf=(float*)(smc+P0);
    const float* xs=smf+P_X/4;
    int mw=w&1, nw=w>>1;
#pragma unroll 1
    for(int half=0;half<2;half++){
        float ac[2][8][4];
#pragma unroll
        for(int mt=0;mt<2;mt++)
#pragma unroll
            for(int s=0;s<8;s++){ac[mt][s][0]=0;ac[mt][s][1]=0;ac[mt][s][2]=0;ac[mt][s][3]=0;}
        float4 rG[8];
        auto ldg_=[&](int kc){
#pragma unroll
            for(int u=0;u<8;u++){int sl=u*NTHR+tid;int r=sl>>3;int cq=(sl&7)*4;
                int wr=(r>>7)*256+128*half+(r&127);
                rG[u]=*(const float4*)(Whh+(size_t)wr*128+kc*32+cq);}
        };
        ldg_(0);
#pragma unroll 1
        for(int kc=0;kc<4;kc++){
#pragma unroll
            for(int u=0;u<8;u++){int sl=u*NTHR+tid;int r=sl>>3;int cq=(sl&7)*4;
                u32 h0v,l0v,h1v,l1v; cvt2(rG[u].x,rG[u].y,h0v,l0v); cvt2(rG[u].z,rG[u].w,h1v,l1v);
                char* p=smc+GB+r*80+cq*2;
                *(uint2*)p=make_uint2(h0v,h1v); *(uint2*)(p+20480)=make_uint2(l0v,l1v);}
            __syncthreads();
            if(kc<3) ldg_(kc+1);
            const char* Ah=smc+P1+kc*10240; const char* Bh=smc+GB;
#pragma unroll
            for(int kh=0;kh<2;kh++){
                u32 ah[2][4],al[2][4];
#pragma unroll
                for(int mt=0;mt<2;mt++){
                    int ar=32*mw+16*mt+(lane>>2);
                    int ao=ar*80+(kh*16+(lane&3)*2)*2;
                    ah[mt][0]=*(const u32*)(Ah+ao);      ah[mt][1]=*(const u32*)(Ah+ao+640);
                    ah[mt][2]=*(const u32*)(Ah+ao+16);   ah[mt][3]=*(const u32*)(Ah+ao+656);
                    al[mt][0]=*(const u32*)(Ah+ao+5120); al[mt][1]=*(const u32*)(Ah+ao+5760);
                    al[mt][2]=*(const u32*)(Ah+ao+5136); al[mt][3]=*(const u32*)(Ah+ao+5776);
                }
#pragma unroll
                for(int s=0;s<8;s++){
                    int bn=64*nw+8*s+(lane>>2);
                    int bo=bn*80+(kh*16+(lane&3)*2)*2;
                    u32 bh0=*(const u32*)(Bh+bo),       bh1=*(const u32*)(Bh+bo+16);
                    u32 bl0=*(const u32*)(Bh+bo+20480), bl1=*(const u32*)(Bh+bo+20496);
#pragma unroll
                    for(int mt=0;mt<2;mt++){
                        mma8(ac[mt][s],ah[mt],bh0,bh1);
                        mma8(ac[mt][s],ah[mt],bl0,bl1);
                        mma8(ac[mt][s],al[mt],bh0,bh1);
                    }
                }
            }
            __syncthreads();
        }
        if(half==0){
            // store i,g (+bias+x*wih) to gif
#pragma unroll
            for(int mt=0;mt<2;mt++)
#pragma unroll
                for(int s=0;s<8;s++){
                    int row=32*mw+16*mt+(lane>>2);
                    int col=64*nw+8*s+(lane&3)*2;
                    int gc=(col<128)?col:(128+col);
#pragma unroll
                    for(int rr=0;rr<2;rr++){
                        int r2=row+rr*8;
                        float xv=xs[r2];
                        float a0=smf[P_BS/4+gc]+xv*smf[P_WIH/4+gc];
                        float a1=smf[P_BS/4+gc+1]+xv*smf[P_WIH/4+gc+1];
                        gif[r2*260+col]=ac[mt][s][rr*2]+a0;
                        gif[r2*260+col+1]=ac[mt][s][rr*2+1]+a1;
                    }
                }
        } else {
            __syncthreads();
            if(nw<2){ // f-warps: c_new
#pragma unroll
                for(int mt=0;mt<2;mt++)
#pragma unroll
                    for(int s=0;s<8;s++){
                        int row=32*mw+16*mt+(lane>>2);
                        int col=64*nw+8*s+(lane&3)*2;   // <128
                        int gc=128+col;
#pragma unroll
                        for(int rr=0;rr<2;rr++){
                            int r2=row+rr*8; float xv=xs[r2];
#pragma unroll
                            for(int e=0;e<2;e++){
                                float F=ac[mt][s][rr*2+e]+smf[P_BS/4+gc+e]+xv*smf[P_WIH/4+gc+e];
                                float I=gif[r2*260+col+e];
                                float G=gif[r2*260+128+col+e];
                                float P=pcf[r2*132+col+e];
                                float cn=sigmf(F)*P+sigmf(I)*tanhf(G);
                                gif[r2*260+col+e]=cn;
                                g_c[k][b0+r2][col+e]=cn;
                            }
                        }
                    }
            }
            __syncthreads();
            if(nw>=2){ // o-warps: h_new
#pragma unroll
                for(int mt=0;mt<2;mt++)
#pragma unroll
                    for(int s=0;s<8;s++){
                        int row=32*mw+16*mt+(lane>>2);
                        int col=64*nw+8*s+(lane&3)*2;   // 128..255
                        int c2=col-128; int gc=256+col;
#pragma unroll
                        for(int rr=0;rr<2;rr++){
                            int r2=row+rr*8; float xv=xs[r2];
#pragma unroll
                            for(int e=0;e<2;e++){
                                float O=ac[mt][s][rr*2+e]+smf[P_BS/4+gc+e]+xv*smf[P_WIH/4+gc+e];
                                float cn=gif[r2*260+c2+e];
                                g_h[k][b0+r2][c2+e]=sigmf(O)*tanhf(cn);
                            }
                        }
                    }
            }
        }
    }
}

// ---------------- head kernels ----------------
__global__ void z_kernel(const float* __restrict__ h_ext,const float* __restrict__ c_ext){
    int idx=blockIdx.x*256+threadIdx.x;
    int b=idx>>8, c=idx&255;
    float v;
    if(c<128) v=g_h[80][b][c]+h_ext[b*128+c];
    else      v=g_c[80][b][c-128]+c_ext[b*128+c-128];
    g_z[b][c]=v;
}

__global__ void __launch_bounds__(256,1) head_gemm(
    const float* __restrict__ A,const float* __restrict__ W,
    const float* __restrict__ bias,float* __restrict__ C,int N,int K)
{
    __shared__ float A_s[64*33];
    __shared__ float W_s[128*33];
    int tid=threadIdx.x, ty=tid&15, tx=tid>>4;
    int b0=blockIdx.x*64, n0=blockIdx.y*128;
    float acc[4][8];
#pragma unroll
    for(int r=0;r<4;r++)
#pragma unroll
        for(int c=0;c<8;c++) acc[r][c]=0.f;
    int nk=K>>5;
#pragma unroll 1
    for(int kc=0;kc<nk;kc++){
#pragma unroll
        for(int it=0;it<2;it++){
            int idx=it*256+tid; int r=idx>>3; int c4=(idx&7)<<2;
            float4 v=*(const float4*)(A+(size_t)(b0+r)*K+(kc<<5)+c4);
            float* p=&A_s[r*33+c4]; p[0]=v.x;p[1]=v.y;p[2]=v.z;p[3]=v.w;
        }
#pragma unroll
        for(int it=0;it<4;it++){
            int idx=it*256+tid; int n=idx>>3; int c4=(idx&7)<<2;
            float4 v=*(const float4*)(W+(size_t)(n0+n)*K+(kc<<5)+c4);
            float* p=&W_s[n*33+c4]; p[0]=v.x;p[1]=v.y;p[2]=v.z;p[3]=v.w;
        }
        __syncthreads();
#pragma unroll 4
        for(int kk=0;kk<32;kk++){
            float a[4],wv[8];
#pragma unroll
            for(int r=0;r<4;r++) a[r]=A_s[(ty*4+r)*33+kk];
#pragma unroll
            for(int c=0;c<8;c++) wv[c]=W_s[(tx*8+c)*33+kk];
#pragma unroll
            for(int r=0;r<4;r++)
#pragma unroll
                for(int c=0;c<8;c++) acc[r][c]=fmaf(a[r],wv[c],acc[r][c]);
        }
        __syncthreads();
    }
#pragma unroll
    for(int r=0;r<4;r++)
#pragma unroll
        for(int c=0;c<8;c++)
            C[(size_t)(b0+ty*4+r)*N+n0+tx*8+c]=acc[r][c]+bias[n0+tx*8+c];
}

__global__ void bn_stats_kernel(const float* __restrict__ Y,int N){
    __shared__ float ss[256],qq[256];
    int col=blockIdx.x, tid=threadIdx.x;
    float s=0.f,q=0.f;
    for(int r=tid;r<B_TOT;r+=256){ float v=Y[(size_t)r*N+col]; s+=v; q+=v*v; }
    ss[tid]=s; qq[tid]=q; __syncthreads();
    for(int o=128;o;o>>=1){ if(tid<o){ ss[tid]+=ss[tid+o]; qq[tid]+=qq[tid+o]; } __syncthreads(); }
    if(tid==0){
        float mu=ss[0]*(1.f/(float)B_TOT);
        float var=qq[0]*(1.f/(float)B_TOT)-mu*mu;
        g_mu[col]=mu; g_rstd[col]=rsqrtf(var+LN_EPS);
    }
}

__global__ void bn_relu_kernel(float* __restrict__ Y,const float* __restrict__ g,
                               const float* __restrict__ b,int N){
    int idx=blockIdx.x*256+threadIdx.x;
    int c=idx&(N-1);
    float v=(Y[idx]-g_mu[c])*g_rstd[c]*g[c]+b[c];
    Y[idx]=fmaxf(v,0.f);
}

__global__ void fc3_kernel(const float* __restrict__ W,const float* __restrict__ bias){
    int row=(blockIdx.x*blockDim.x+threadIdx.x)>>5;
    int lane=threadIdx.x&31;
    float s=0.f;
#pragma unroll
    for(int c=lane;c<128;c+=32) s+=g_y2[row][c]*W[c];
#pragma unroll
    for(int o=16;o;o>>=1) s+=__shfl_xor_sync(~0u,s,o);
    if(lane==0) g_y3[row]=s+bias[0];
}

__global__ void final_kernel(const float* __restrict__ g,const float* __restrict__ b,
                             float* __restrict__ out){
    __shared__ float ss[1024],qq[1024];
    int tid=threadIdx.x;
    float s=0.f,q=0.f;
    for(int r=tid;r<B_TOT;r+=1024){ float v=g_y3[r]; s+=v; q+=v*v; }
    ss[tid]=s; qq[tid]=q; __syncthreads();
    for(int o=512;o;o>>=1){ if(tid<o){ ss[tid]+=ss[tid+o]; qq[tid]+=qq[tid+o]; } __syncthreads(); }
    float mu=ss[0]*(1.f/(float)B_TOT);
    float var=qq[0]*(1.f/(float)B_TOT)-mu*mu;
    float rs=rsqrtf(var+LN_EPS);
    float gg=g[0], bb=b[0];
    for(int r=tid;r<B_TOT;r+=1024){
        float v=(g_y3[r]-mu)*rs*gg+bb;
        out[r]=1.f/(1.f+expf(-v));
    }
}

extern "C" void kernel_launch(void* const* d_in,const int* in_sizes,int n_in,
                              void* d_out,int out_size)
{
    const float* x     =(const float*)d_in[0];
    const float* h_ext =(const float*)d_in[1];
    const float* c_ext =(const float*)d_in[2];
    const float* h_g0  =(const float*)d_in[3];
    const float* c_g0  =(const float*)d_in[4];
    const float* Wh    =(const float*)d_in[5];
    const float* bh    =(const float*)d_in[6];
    const float* Wc    =(const float*)d_in[7];
    const float* bc    =(const float*)d_in[8];
    const float* lnh_g =(const float*)d_in[9];
    const float* lnh_b =(const float*)d_in[10];
    const float* lnc_g =(const float*)d_in[11];
    const float* lnc_b =(const float*)d_in[12];
    const float* W_ih  =(const float*)d_in[13];
    const float* b_ih  =(const float*)d_in[14];
    const float* W_hh  =(const float*)d_in[15];
    const float* b_hh  =(const float*)d_in[16];
    const float* fc1W  =(const float*)d_in[17];
    const float* fc1b  =(const float*)d_in[18];
    const float* bn1g  =(const float*)d_in[19];
    const float* bn1b  =(const float*)d_in[20];
    const float* fc2W  =(const float*)d_in[21];
    const float* fc2b  =(const float*)d_in[22];
    const float* bn2g  =(const float*)d_in[23];
    const float* bn2b  =(const float*)d_in[24];
    const float* fc3W  =(const float*)d_in[25];
    const float* fc3b  =(const float*)d_in[26];
    const float* bnog  =(const float*)d_in[27];
    const float* bnob  =(const float*)d_in[28];
    float* out=(float*)d_out;

    cudaFuncSetAttribute(cell_kernel, cudaFuncAttributeMaxDynamicSharedMemorySize, SMEM_TOTAL);

    for(int d=0; d<=16; d++){
        int ilo=d>8?d-8:0, ihi=d<8?d:8;
        int nc=ihi-ilo+1;
        cell_kernel<<<dim3(64,nc), NTHR, SMEM_TOTAL>>>(
            x,h_ext,c_ext,h_g0,c_g0,Wh,bh,Wc,bc,
            lnh_g,lnh_b,lnc_g,lnc_b,W_ih,b_ih,W_hh,b_hh,d);
    }

    float *zp,*y1p,*y2p;
    cudaGetSymbolAddress((void**)&zp, g_z);
    cudaGetSymbolAddress((void**)&y1p,g_y1);
    cudaGetSymbolAddress((void**)&y2p,g_y2);

    z_kernel<<<4096,256>>>(h_ext,c_ext);
    head_gemm<<<dim3(64,2),256>>>(zp,fc1W,fc1b,y1p,256,256);
    bn_stats_kernel<<<256,256>>>(y1p,256);
    bn_relu_kernel<<<4096,256>>>(y1p,bn1g,bn1b,256);
    head_gemm<<<dim3(64,1),256>>>(y1p,fc2W,fc2b,y2p,128,256);
    bn_stats_kernel<<<128,256>>>(y2p,128);
    bn_relu_kernel<<<2048,256>>>(y2p,bn2g,bn2b,128);
    fc3_kernel<<<512,256>>>(fc3W,fc3b);
    final_kernel<<<1,1024>>>(bnog,bnob,out);
}

// round 11
// speedup vs baseline: 1.7297x; 1.2600x over previous
#include <cuda_runtime.h>
#include <cuda_fp16.h>
#include <cstdint>
typedef uint32_t u32;

#define B_TOT 4096
#define NCELL 81
#define LN_EPS 1e-5f
#define NTHR 512

__device__ float g_h[NCELL][B_TOT][128];
__device__ float g_c[NCELL][B_TOT][128];
__device__ float g_z [B_TOT][256];
__device__ float g_y1[B_TOT][256];
__device__ float g_y2[B_TOT][128];
__device__ float g_y3[B_TOT];
__device__ float g_mu[256];
__device__ float g_rstd[256];

__device__ __forceinline__ float sigmf(float v){ return 1.f/(1.f+expf(-v)); }

// ---- smem byte offsets (unchanged layout) ----
#define P_BS  0
#define P_WIH 2048
#define P_X   4096
#define P_BH  4352
#define P_BC  4864
#define P_LHG 5376
#define P_LHB 5888
#define P_LCG 6400
#define P_LCB 6912
#define P0 8448            // staging fp32, pitch 132 floats (64 rows)
#define P1 42240           // ph fp16 chunks: chunk c: hi P1+c*10240, lo +5120
#define P2 83200           // main A/B double buffers; gates B overlays
#define P3 144640          // gate_if fp32 pitch 260 floats
#define SMEM_TOTAL 211200
#define AB(i) (P2 + (i)*10240)
#define BB(i) (P2 + 20480 + (i)*20480)
#define GB    (P2)

__device__ __forceinline__ void mma8(float* d,const u32* a,u32 b0,u32 b1){
    asm volatile("mma.sync.aligned.m16n8k16.row.col.f32.f16.f16.f32 "
        "{%0,%1,%2,%3},{%4,%5,%6,%7},{%8,%9},{%0,%1,%2,%3};"
        : "+f"(d[0]),"+f"(d[1]),"+f"(d[2]),"+f"(d[3])
        : "r"(a[0]),"r"(a[1]),"r"(a[2]),"r"(a[3]),"r"(b0),"r"(b1));
}
__device__ __forceinline__ void cvt2(float ax,float ay,u32&H,u32&L){
    __half2 h=__floats2half2_rn(ax,ay);
    float2 f=__half22float2(h);
    __half2 l=__floats2half2_rn(ax-f.x,ay-f.y);
    H=*(u32*)&h; L=*(u32*)&l;
}

// main GEMM: [64,384]x[384,128]^T -> staging fp32 (P0) + bias
// 16 warps: m-group = w>>2 (16 rows), n-group = w&3 (32 cols, 4 s-tiles)
__device__ __forceinline__ void main_gemm(char* smc,
    const float* s0,const float* s1,const float* s2,
    const float* __restrict__ Wk,int b0,int tid,int lane,int w,int biasOff)
{
    const float* srcs[3]={s0,s1,s2};
    float acc[4][4];
#pragma unroll
    for(int s=0;s<4;s++){acc[s][0]=0;acc[s][1]=0;acc[s][2]=0;acc[s][3]=0;}
    float4 rA, rW[2];
    auto ldc=[&](int kc){
        const float* s=srcs[kc>>2]; int cb=(kc&3)*32;
        { int sl=tid; int row=sl>>3; int cq=(sl&7)*4;
          rA = s? *(const float4*)(s+(size_t)(b0+row)*128+cb+cq):make_float4(0,0,0,0); }
#pragma unroll
        for(int u=0;u<2;u++){int sl=u*NTHR+tid;int n=sl>>3;int cq=(sl&7)*4;
            rW[u]=*(const float4*)(Wk+(size_t)n*384+kc*32+cq);}
    };
    auto sts=[&](int buf){
        { int sl=tid; int row=sl>>3; int cq=(sl&7)*4;
          u32 h0,l0,h1,l1; cvt2(rA.x,rA.y,h0,l0); cvt2(rA.z,rA.w,h1,l1);
          char* p=smc+AB(buf)+row*80+cq*2;
          *(uint2*)p=make_uint2(h0,h1); *(uint2*)(p+5120)=make_uint2(l0,l1); }
#pragma unroll
        for(int u=0;u<2;u++){int sl=u*NTHR+tid;int n=sl>>3;int cq=(sl&7)*4;
            u32 h0,l0,h1,l1; cvt2(rW[u].x,rW[u].y,h0,l0); cvt2(rW[u].z,rW[u].w,h1,l1);
            char* p=smc+BB(buf)+n*80+cq*2;
            *(uint2*)p=make_uint2(h0,h1); *(uint2*)(p+10240)=make_uint2(l0,l1);}
    };
    ldc(0); sts(0); __syncthreads();
#pragma unroll 1
    for(int kc=0;kc<12;kc++){
        if(kc<11) ldc(kc+1);
        const char* Ah=smc+AB(kc&1); const char* Bh=smc+BB(kc&1);
        int ar=16*(w>>2)+(lane>>2);
#pragma unroll
        for(int kh=0;kh<2;kh++){
            int ao=ar*80+(kh*16+(lane&3)*2)*2;
            u32 ah[4],al[4];
            ah[0]=*(const u32*)(Ah+ao);      ah[1]=*(const u32*)(Ah+ao+640);
            ah[2]=*(const u32*)(Ah+ao+16);   ah[3]=*(const u32*)(Ah+ao+656);
            al[0]=*(const u32*)(Ah+ao+5120); al[1]=*(const u32*)(Ah+ao+5760);
            al[2]=*(const u32*)(Ah+ao+5136); al[3]=*(const u32*)(Ah+ao+5776);
#pragma unroll
            for(int s=0;s<4;s++){
                int bn=32*(w&3)+8*s+(lane>>2);
                int bo=bn*80+(kh*16+(lane&3)*2)*2;
                u32 bh0=*(const u32*)(Bh+bo),       bh1=*(const u32*)(Bh+bo+16);
                u32 bl0=*(const u32*)(Bh+bo+10240), bl1=*(const u32*)(Bh+bo+10256);
                mma8(acc[s],ah,bh0,bh1);
                mma8(acc[s],ah,bl0,bl1);
                mma8(acc[s],al,bh0,bh1);
            }
        }
        if(kc<11) sts((kc+1)&1);
        __syncthreads();
    }
    float* pcf=(float*)(smc+P0);
    const float* bias=(const float*)(smc+biasOff);
    int r=16*(w>>2)+(lane>>2);
#pragma unroll
    for(int s=0;s<4;s++){
        int c=32*(w&3)+8*s+(lane&3)*2;
        pcf[r*132+c]=acc[s][0]+bias[c];     pcf[r*132+c+1]=acc[s][1]+bias[c+1];
        pcf[(r+8)*132+c]=acc[s][2]+bias[c]; pcf[(r+8)*132+c+1]=acc[s][3]+bias[c+1];
    }
}

// LN over P0; 16 warps x 4 rows
__device__ __forceinline__ void ln_pass(char* smc,int lane,int w,int gOff,int bOff,int toHalf){
    float* pcf=(float*)(smc+P0);
    const float* g=(const float*)(smc+gOff); const float* b=(const float*)(smc+bOff);
#pragma unroll 1
    for(int rr=0;rr<4;rr++){
        int r=w*4+rr;
        float v[4];
#pragma unroll
        for(int q=0;q<4;q++) v[q]=pcf[r*132+lane+32*q];
        float s=v[0]+v[1]+v[2]+v[3];
        float qq=v[0]*v[0]+v[1]*v[1]+v[2]*v[2]+v[3]*v[3];
#pragma unroll
        for(int o=16;o;o>>=1){ s+=__shfl_xor_sync(~0u,s,o); qq+=__shfl_xor_sync(~0u,qq,o); }
        float mu=s*(1.f/128.f), var=qq*(1.f/128.f)-mu*mu, rs=rsqrtf(var+LN_EPS);
#pragma unroll
        for(int q=0;q<4;q++){
            float nv=(v[q]-mu)*rs*g[lane+32*q]+b[lane+32*q];
            if(toHalf){
                __half hh=__float2half_rn(nv);
                __half hl=__float2half_rn(nv-__half2float(hh));
                *(__half*)(smc+P1+q*10240+r*80+lane*2)=hh;
                *(__half*)(smc+P1+q*10240+5120+r*80+lane*2)=hl;
            } else pcf[r*132+lane+32*q]=nv;
        }
    }
}

__global__ void __launch_bounds__(NTHR) cell_kernel(
    const float* __restrict__ x,
    const float* __restrict__ h_ext,const float* __restrict__ c_ext,
    const float* __restrict__ h_grid0,const float* __restrict__ c_grid0,
    const float* __restrict__ Wh,const float* __restrict__ bh,
    const float* __restrict__ Wc,const float* __restrict__ bc,
    const float* __restrict__ lnh_g,const float* __restrict__ lnh_b,
    const float* __restrict__ lnc_g,const float* __restrict__ lnc_b,
    const float* __restrict__ W_ih,const float* __restrict__ b_ih,
    const float* __restrict__ W_hh,const float* __restrict__ b_hh,int diag)
{
    extern __shared__ char smc[];
    float* smf=(float*)smc;
    int tid=threadIdx.x, lane=tid&31, w=tid>>5;
    int b0=blockIdx.x<<6;
    int i0=diag>8?diag-8:0;
    int i=i0+blockIdx.y, j=diag-i, k=i*9+j;

    {
        const float* bihp=b_ih+k*512; const float* bhhp=b_hh+k*512; const float* wihp=W_ih+k*512;
        if(tid<512){ smf[P_BS/4+tid]=bihp[tid]+bhhp[tid]; smf[P_WIH/4+tid]=wihp[tid]; }
        if(tid<64) smf[P_X/4+tid]=x[(size_t)(b0+tid)*81+k];
        if(tid>=128&&tid<256){int t=tid-128;
            smf[P_BH/4+t]=bh[k*128+t];    smf[P_BC/4+t]=bc[k*128+t];
            smf[P_LHG/4+t]=lnh_g[k*128+t];smf[P_LHB/4+t]=lnh_b[k*128+t];
            smf[P_LCG/4+t]=lnc_g[k*128+t];smf[P_LCB/4+t]=lnc_b[k*128+t];
        }
    }
    const float *h0,*c0,*h1,*c1;
    if(j>0){ h0=&g_h[k-1][0][0]; c0=&g_c[k-1][0][0]; }
    else if(i==0){ h0=h_ext; c0=c_ext; }
    else { h0=0; c0=0; }
    if(i>0){ h1=&g_h[k-9][0][0]; c1=&g_c[k-9][0][0]; } else { h1=0; c1=0; }
    const float* h2=h_grid0+(size_t)k*B_TOT*128;
    const float* c2=c_grid0+(size_t)k*B_TOT*128;
    __syncthreads();

    // h GEMM -> LN -> fp16 chunks (gates A)
    main_gemm(smc,h0,h1,h2,Wh+(size_t)k*49152,b0,tid,lane,w,P_BH);
    __syncthreads();
    ln_pass(smc,lane,w,P_LHG,P_LHB,1);
    __syncthreads();
    // c GEMM -> LN -> fp32 in P0
    main_gemm(smc,c0,c1,c2,Wc+(size_t)k*49152,b0,tid,lane,w,P_BC);
    __syncthreads();
    ln_pass(smc,lane,w,P_LCG,P_LCB,0);
    __syncthreads();

    // gates: half0 = i,g ; half1 = f,o.  16 warps: mw=w&3 (16 rows), nw=w>>2 (64 cols)
    const float* Whh=W_hh+(size_t)k*65536;
    float* gif=(float*)(smc+P3);
    float* pcf=(float*)(smc+P0);
    const float* xs=smf+P_X/4;
    int mw=w&3, nw=w>>2;
#pragma unroll 1
    for(int half=0;half<2;half++){
        float ac[8][4];
#pragma unroll
        for(int s=0;s<8;s++){ac[s][0]=0;ac[s][1]=0;ac[s][2]=0;ac[s][3]=0;}
        float4 rG[4];
        auto ldg_=[&](int kc){
#pragma unroll
            for(int u=0;u<4;u++){int sl=u*NTHR+tid;int r=sl>>3;int cq=(sl&7)*4;
                int wr=(r>>7)*256+128*half+(r&127);
                rG[u]=*(const float4*)(Whh+(size_t)wr*128+kc*32+cq);}
        };
        ldg_(0);
#pragma unroll 1
        for(int kc=0;kc<4;kc++){
#pragma unroll
            for(int u=0;u<4;u++){int sl=u*NTHR+tid;int r=sl>>3;int cq=(sl&7)*4;
                u32 h0v,l0v,h1v,l1v; cvt2(rG[u].x,rG[u].y,h0v,l0v); cvt2(rG[u].z,rG[u].w,h1v,l1v);
                char* p=smc+GB+r*80+cq*2;
                *(uint2*)p=make_uint2(h0v,h1v); *(uint2*)(p+20480)=make_uint2(l0v,l1v);}
            __syncthreads();
            if(kc<3) ldg_(kc+1);
            const char* Ah=smc+P1+kc*10240; const char* Bh=smc+GB;
#pragma unroll
            for(int kh=0;kh<2;kh++){
                int ar=16*mw+(lane>>2);
                int ao=ar*80+(kh*16+(lane&3)*2)*2;
                u32 ah[4],al[4];
                ah[0]=*(const u32*)(Ah+ao);      ah[1]=*(const u32*)(Ah+ao+640);
                ah[2]=*(const u32*)(Ah+ao+16);   ah[3]=*(const u32*)(Ah+ao+656);
                al[0]=*(const u32*)(Ah+ao+5120); al[1]=*(const u32*)(Ah+ao+5760);
                al[2]=*(const u32*)(Ah+ao+5136); al[3]=*(const u32*)(Ah+ao+5776);
#pragma unroll
                for(int s=0;s<8;s++){
                    int bn=64*nw+8*s+(lane>>2);
                    int bo=bn*80+(kh*16+(lane&3)*2)*2;
                    u32 bh0=*(const u32*)(Bh+bo),       bh1=*(const u32*)(Bh+bo+16);
                    u32 bl0=*(const u32*)(Bh+bo+20480), bl1=*(const u32*)(Bh+bo+20496);
                    mma8(ac[s],ah,bh0,bh1);
                    mma8(ac[s],ah,bl0,bl1);
                    mma8(ac[s],al,bh0,bh1);
                }
            }
            __syncthreads();
        }
        if(half==0){
#pragma unroll
            for(int s=0;s<8;s++){
                int row=16*mw+(lane>>2);
                int col=64*nw+8*s+(lane&3)*2;
                int gc=(col<128)?col:(128+col);
#pragma unroll
                for(int rr=0;rr<2;rr++){
                    int r2=row+rr*8;
                    float xv=xs[r2];
                    float a0=smf[P_BS/4+gc]+xv*smf[P_WIH/4+gc];
                    float a1=smf[P_BS/4+gc+1]+xv*smf[P_WIH/4+gc+1];
                    gif[r2*260+col]=ac[s][rr*2]+a0;
                    gif[r2*260+col+1]=ac[s][rr*2+1]+a1;
                }
            }
        } else {
            __syncthreads();
            if(nw<2){ // f-warps: c_new (cols 0..127)
#pragma unroll
                for(int s=0;s<8;s++){
                    int row=16*mw+(lane>>2);
                    int col=64*nw+8*s+(lane&3)*2;
                    int gc=128+col;
#pragma unroll
                    for(int rr=0;rr<2;rr++){
                        int r2=row+rr*8; float xv=xs[r2];
#pragma unroll
                        for(int e=0;e<2;e++){
                            float F=ac[s][rr*2+e]+smf[P_BS/4+gc+e]+xv*smf[P_WIH/4+gc+e];
                            float I=gif[r2*260+col+e];
                            float G=gif[r2*260+128+col+e];
                            float P=pcf[r2*132+col+e];
                            float cn=sigmf(F)*P+sigmf(I)*tanhf(G);
                            gif[r2*260+col+e]=cn;
                            g_c[k][b0+r2][col+e]=cn;
                        }
                    }
                }
            }
            __syncthreads();
            if(nw>=2){ // o-warps: h_new (cols 128..255)
#pragma unroll
                for(int s=0;s<8;s++){
                    int row=16*mw+(lane>>2);
                    int col=64*nw+8*s+(lane&3)*2;
                    int c2=col-128; int gc=256+col;
#pragma unroll
                    for(int rr=0;rr<2;rr++){
                        int r2=row+rr*8; float xv=xs[r2];
#pragma unroll
                        for(int e=0;e<2;e++){
                            float O=ac[s][rr*2+e]+smf[P_BS/4+gc+e]+xv*smf[P_WIH/4+gc+e];
                            float cn=gif[r2*260+c2+e];
                            g_h[k][b0+r2][c2+e]=sigmf(O)*tanhf(cn);
                        }
                    }
                }
            }
        }
    }
}

// ---------------- head kernels ----------------
__global__ void z_kernel(const float* __restrict__ h_ext,const float* __restrict__ c_ext){
    int idx=blockIdx.x*256+threadIdx.x;
    int b=idx>>8, c=idx&255;
    float v;
    if(c<128) v=g_h[80][b][c]+h_ext[b*128+c];
    else      v=g_c[80][b][c-128]+c_ext[b*128+c-128];
    g_z[b][c]=v;
}

__global__ void __launch_bounds__(256,1) head_gemm(
    const float* __restrict__ A,const float* __restrict__ W,
    const float* __restrict__ bias,float* __restrict__ C,int N,int K)
{
    __shared__ float A_s[64*33];
    __shared__ float W_s[128*33];
    int tid=threadIdx.x, ty=tid&15, tx=tid>>4;
    int b0=blockIdx.x*64, n0=blockIdx.y*128;
    float acc[4][8];
#pragma unroll
    for(int r=0;r<4;r++)
#pragma unroll
        for(int c=0;c<8;c++) acc[r][c]=0.f;
    int nk=K>>5;
#pragma unroll 1
    for(int kc=0;kc<nk;kc++){
#pragma unroll
        for(int it=0;it<2;it++){
            int idx=it*256+tid; int r=idx>>3; int c4=(idx&7)<<2;
            float4 v=*(const float4*)(A+(size_t)(b0+r)*K+(kc<<5)+c4);
            float* p=&A_s[r*33+c4]; p[0]=v.x;p[1]=v.y;p[2]=v.z;p[3]=v.w;
        }
#pragma unroll
        for(int it=0;it<4;it++){
            int idx=it*256+tid; int n=idx>>3; int c4=(idx&7)<<2;
            float4 v=*(const float4*)(W+(size_t)(n0+n)*K+(kc<<5)+c4);
            float* p=&W_s[n*33+c4]; p[0]=v.x;p[1]=v.y;p[2]=v.z;p[3]=v.w;
        }
        __syncthreads();
#pragma unroll 4
        for(int kk=0;kk<32;kk++){
            float a[4],wv[8];
#pragma unroll
            for(int r=0;r<4;r++) a[r]=A_s[(ty*4+r)*33+kk];
#pragma unroll
            for(int c=0;c<8;c++) wv[c]=W_s[(tx*8+c)*33+kk];
#pragma unroll
            for(int r=0;r<4;r++)
#pragma unroll
                for(int c=0;c<8;c++) acc[r][c]=fmaf(a[r],wv[c],acc[r][c]);
        }
        __syncthreads();
    }
#pragma unroll
    for(int r=0;r<4;r++)
#pragma unroll
        for(int c=0;c<8;c++)
            C[(size_t)(b0+ty*4+r)*N+n0+tx*8+c]=acc[r][c]+bias[n0+tx*8+c];
}

__global__ void bn_stats_kernel(const float* __restrict__ Y,int N){
    __shared__ float ss[256],qq[256];
    int col=blockIdx.x, tid=threadIdx.x;
    float s=0.f,q=0.f;
    for(int r=tid;r<B_TOT;r+=256){ float v=Y[(size_t)r*N+col]; s+=v; q+=v*v; }
    ss[tid]=s; qq[tid]=q; __syncthreads();
    for(int o=128;o;o>>=1){ if(tid<o){ ss[tid]+=ss[tid+o]; qq[tid]+=qq[tid+o]; } __syncthreads(); }
    if(tid==0){
        float mu=ss[0]*(1.f/(float)B_TOT);
        float var=qq[0]*(1.f/(float)B_TOT)-mu*mu;
        g_mu[col]=mu; g_rstd[col]=rsqrtf(var+LN_EPS);
    }
}

__global__ void bn_relu_kernel(float* __restrict__ Y,const float* __restrict__ g,
                               const float* __restrict__ b,int N){
    int idx=blockIdx.x*256+threadIdx.x;
    int c=idx&(N-1);
    float v=(Y[idx]-g_mu[c])*g_rstd[c]*g[c]+b[c];
    Y[idx]=fmaxf(v,0.f);
}

__global__ void fc3_kernel(const float* __restrict__ W,const float* __restrict__ bias){
    int row=(blockIdx.x*blockDim.x+threadIdx.x)>>5;
    int lane=threadIdx.x&31;
    float s=0.f;
#pragma unroll
    for(int c=lane;c<128;c+=32) s+=g_y2[row][c]*W[c];
#pragma unroll
    for(int o=16;o;o>>=1) s+=__shfl_xor_sync(~0u,s,o);
    if(lane==0) g_y3[row]=s+bias[0];
}

__global__ void final_kernel(const float* __restrict__ g,const float* __restrict__ b,
                             float* __restrict__ out){
    __shared__ float ss[1024],qq[1024];
    int tid=threadIdx.x;
    float s=0.f,q=0.f;
    for(int r=tid;r<B_TOT;r+=1024){ float v=g_y3[r]; s+=v; q+=v*v; }
    ss[tid]=s; qq[tid]=q; __syncthreads();
    for(int o=512;o;o>>=1){ if(tid<o){ ss[tid]+=ss[tid+o]; qq[tid]+=qq[tid+o]; } __syncthreads(); }
    float mu=ss[0]*(1.f/(float)B_TOT);
    float var=qq[0]*(1.f/(float)B_TOT)-mu*mu;
    float rs=rsqrtf(var+LN_EPS);
    float gg=g[0], bb=b[0];
    for(int r=tid;r<B_TOT;r+=1024){
        float v=(g_y3[r]-mu)*rs*gg+bb;
        out[r]=1.f/(1.f+expf(-v));
    }
}

extern "C" void kernel_launch(void* const* d_in,const int* in_sizes,int n_in,
                              void* d_out,int out_size)
{
    const float* x     =(const float*)d_in[0];
    const float* h_ext =(const float*)d_in[1];
    const float* c_ext =(const float*)d_in[2];
    const float* h_g0  =(const float*)d_in[3];
    const float* c_g0  =(const float*)d_in[4];
    const float* Wh    =(const float*)d_in[5];
    const float* bh    =(const float*)d_in[6];
    const float* Wc    =(const float*)d_in[7];
    const float* bc    =(const float*)d_in[8];
    const float* lnh_g =(const float*)d_in[9];
    const float* lnh_b =(const float*)d_in[10];
    const float* lnc_g =(const float*)d_in[11];
    const float* lnc_b =(const float*)d_in[12];
    const float* W_ih  =(const float*)d_in[13];
    const float* b_ih  =(const float*)d_in[14];
    const float* W_hh  =(const float*)d_in[15];
    const float* b_hh  =(const float*)d_in[16];
    const float* fc1W  =(const float*)d_in[17];
    const float* fc1b  =(const float*)d_in[18];
    const float* bn1g  =(const float*)d_in[19];
    const float* bn1b  =(const float*)d_in[20];
    const float* fc2W  =(const float*)d_in[21];
    const float* fc2b  =(const float*)d_in[22];
    const float* bn2g  =(const float*)d_in[23];
    const float* bn2b  =(const float*)d_in[24];
    const float* fc3W  =(const float*)d_in[25];
    const float* fc3b  =(const float*)d_in[26];
    const float* bnog  =(const float*)d_in[27];
    const float* bnob  =(const float*)d_in[28];
    float* out=(float*)d_out;

    cudaFuncSetAttribute(cell_kernel, cudaFuncAttributeMaxDynamicSharedMemorySize, SMEM_TOTAL);

    for(int d=0; d<=16; d++){
        int ilo=d>8?d-8:0, ihi=d<8?d:8;
        int nc=ihi-ilo+1;
        cell_kernel<<<dim3(64,nc), NTHR, SMEM_TOTAL>>>(
            x,h_ext,c_ext,h_g0,c_g0,Wh,bh,Wc,bc,
            lnh_g,lnh_b,lnc_g,lnc_b,W_ih,b_ih,W_hh,b_hh,d);
    }

    float *zp,*y1p,*y2p;
    cudaGetSymbolAddress((void**)&zp, g_z);
    cudaGetSymbolAddress((void**)&y1p,g_y1);
    cudaGetSymbolAddress((void**)&y2p,g_y2);

    z_kernel<<<4096,256>>>(h_ext,c_ext);
    head_gemm<<<dim3(64,2),256>>>(zp,fc1W,fc1b,y1p,256,256);
    bn_stats_kernel<<<256,256>>>(y1p,256);
    bn_relu_kernel<<<4096,256>>>(y1p,bn1g,bn1b,256);
    head_gemm<<<dim3(64,1),256>>>(y1p,fc2W,fc2b,y2p,128,256);
    bn_stats_kernel<<<128,256>>>(y2p,128);
    bn_relu_kernel<<<2048,256>>>(y2p,bn2g,bn2b,128);
    fc3_kernel<<<512,256>>>(fc3W,fc3b);
    final_kernel<<<1,1024>>>(bnog,bnob,out);
}